// round 16
// baseline (speedup 1.0000x reference)
#include <cuda_runtime.h>
#include <cuda_fp16.h>
#include <math.h>
#include <stdint.h>

// ---------------- problem constants ----------------
static constexpr int Bn  = 4;
static constexpr int N3  = 128*128*3;        // 49152
static constexpr int N4  = 64*64*3;          // 12288
static constexpr int N5  = 32*32*3;          // 3072
static constexpr int NTOT = N3 + N4 + N5;    // 64512
static constexpr int PRE  = 400;
static constexpr int POST = 100;
static constexpr int CAND = 640;             // approx candidate margin
static constexpr int RSEG = 32;              // rescue candidates per CTA
static constexpr float NMS_T  = 0.7f;
static constexpr float IMGW   = 1024.0f;
static constexpr float IMGH   = 1024.0f;
#define SCLAMP 3.3322045101752038f

// approx conv smem: A 2 stages of [64 px][32 cin] pitch 80B; B 3 stages of [256 cout][32 cin] pitch 80B
static constexpr int APITCH = 80;
static constexpr int A_STG  = 5120;              // 64*80
static constexpr int B_STG  = 20480;             // 256*80
static constexpr int B_BASE = 2*A_STG;           // 10240
static constexpr int ACONV_SMEM = B_BASE + 3*B_STG;   // 71680
// rescue smem: stages As[2][16][256] + Bs[2][16][32]; epilogue st[256][33]+wh[4096]+hs[16*33]
static constexpr int RESCUE_SMEM = (256*33 + 4096 + 16*33) * 4;  // 52288 (> stage 36864)

// ---------------- device scratch (total ~4.7 MiB; big globals trip the mem guard) ----------------
__device__ __align__(128) float  g_wt [9*256*256];  // [pos][cin][cout] exact rescue
__device__ __align__(128) __half g_wfh[9*256*256];  // [pos][cout][cin] fp16 approx
__device__ float g_wh[16*256];        // head rows: 0..2 obj, 3..14 box, 15 zero
__device__ float g_bh[16];
__device__ float g_scores[Bn*NTOT];
__device__ int   g_cidx  [12*CAND];
__device__ float g_cscore[12*CAND];
__device__ float g_cbox  [12*CAND*4];

// packed fp32x2 FMA (exact IEEE per lane)
#define FMA2(ACC, S, B) \
    asm("fma.rn.f32x2 %0, %1, %2, %0;" : "+l"(ACC) : "l"(S), "l"(B))
#define SPLAT2(D, V) \
    asm("mov.b64 %0, {%1, %1};" : "=l"(D) : "r"(__float_as_uint(V)))

// fp16 mma m16n8k16, fp32 accumulate
#define MMAH(C, A0, A1, A2, A3, B0, B1) \
    asm volatile("mma.sync.aligned.m16n8k16.row.col.f32.f16.f16.f32 " \
        "{%0,%1,%2,%3}, {%4,%5,%6,%7}, {%8,%9}, {%0,%1,%2,%3};" \
        : "+f"((C)[0]), "+f"((C)[1]), "+f"((C)[2]), "+f"((C)[3]) \
        : "r"(A0), "r"(A1), "r"(A2), "r"(A3), "r"(B0), "r"(B1))

__device__ __forceinline__ void ldsm4(uint32_t a, uint32_t* r){
    asm volatile("ldmatrix.sync.aligned.m8n8.x4.shared.b16 {%0,%1,%2,%3}, [%4];"
                 : "=r"(r[0]), "=r"(r[1]), "=r"(r[2]), "=r"(r[3]) : "r"(a));
}
__device__ __forceinline__ uint32_t smem_u32(const void* p){
    uint32_t a;
    asm("{ .reg .u64 t; cvta.to.shared.u64 t, %1; cvt.u32.u64 %0, t; }" : "=r"(a) : "l"(p));
    return a;
}
__device__ __forceinline__ void cpa16(uint32_t dst, const void* src){
    asm volatile("cp.async.cg.shared.global [%0], [%1], 16;" :: "r"(dst), "l"(src) : "memory");
}
#define CP_COMMIT() asm volatile("cp.async.commit_group;" ::: "memory")
__device__ __forceinline__ uint32_t packh2(float a, float b){
    __half2 h = __floats2half2_rn(a, b);
    return *reinterpret_cast<uint32_t*>(&h);
}
__device__ __forceinline__ unsigned f2o(float f) {
    unsigned u = __float_as_uint(f);
    return (u & 0x80000000u) ? ~u : (u | 0x80000000u);
}

// ---------------- prep ----------------
__global__ void prep_w(const float* __restrict__ w) {
    int i = blockIdx.x * 256 + threadIdx.x;
    if (i < 9*256*256) {
        int pos  = i >> 16;
        int cin  = (i >> 8) & 255;
        int cout = i & 255;
        float v = w[(cout*256 + cin)*9 + pos];
        g_wt [(pos << 16) | (cin << 8) | cout] = v;
        g_wfh[(pos << 16) | (cout << 8) | cin] = __float2half_rn(v);
    }
}

__global__ void prep_head(const float* __restrict__ wobj, const float* __restrict__ bobj,
                          const float* __restrict__ wbox, const float* __restrict__ bbox) {
    int i = blockIdx.x * 256 + threadIdx.x;
    if (i < 16*256) {
        int o = i >> 8, k = i & 255;
        float v = 0.f;
        if (o < 3)        v = wobj[o*256 + k];
        else if (o < 15)  v = wbox[(o-3)*256 + k];
        g_wh[i] = v;
    }
    if (i < 16) {
        float v = 0.f;
        if (i < 3)        v = bobj[i];
        else if (i < 15)  v = bbox[i-3];
        g_bh[i] = v;
    }
}

// ---------------- approx conv: fp16 mma + ldmatrix, cp.async B, 2-deep A prefetch ----------------
__global__ __launch_bounds__(512)
void aconv_kernel(const float* __restrict__ f3, const float* __restrict__ f4,
                  const float* __restrict__ f5, const float* __restrict__ bstem)
{
    extern __shared__ __align__(128) char smc[];
    const uint32_t smb = smem_u32(smc);
    const int tid  = threadIdx.x;
    const int lane = tid & 31;
    const int wid  = tid >> 5;          // 0..15
    const int mwp  = wid >> 2;          // 0..3 : 16-pixel band
    const int nwp  = wid & 3;           // 0..3 : 64-cout quarter
    const int g    = lane >> 2;         // 0..7
    const int t4   = lane & 3;          // 0..3

    int mt = blockIdx.x;
    int b, tile, S, logS, loff;
    const float* feat;
    if (mt < 1024)      { b = mt >> 8; tile = mt & 255; S=128; logS=7; loff=0;     feat = f3; }
    else if (mt < 1280) { mt -= 1024; b = mt >> 6; tile = mt & 63; S=64; logS=6; loff=N3;    feat = f4; }
    else                { mt -= 1280; b = mt >> 4; tile = mt & 15; S=32; logS=5; loff=N3+N4; feat = f5; }
    const int S2 = S * S;

    const int brow  = tid & 255;        // B loader: cout row
    const int khalf = tid >> 8;         // 0/1: 16-cin half of 32-cin chunk
    const bool isA  = tid < 256;
    const int p  = tid & 63;
    const int cg = (tid >> 6) & 3;      // 8-cin group
    const int pixL = tile*64 + p;
    const int y0 = pixL >> logS;
    const int x0 = pixL & (S - 1);

    float acc[8][4];
    #pragma unroll
    for (int j = 0; j < 8; j++)
        #pragma unroll
        for (int k = 0; k < 4; k++) acc[j][k] = 0.f;

    uint32_t rau[2][4];
    auto loadA = [&](int ck, int buf){
        if (!isA) return;
        const int pos = ck >> 3;
        const int c0  = (ck & 7) << 5;
        const int kh = pos / 3;
        const int dh = kh - 1, dw = pos - kh*3 - 1;
        const int ys = y0 + dh, xs = x0 + dw;
        float v[8];
        if ((unsigned)ys < (unsigned)S && (unsigned)xs < (unsigned)S) {
            const float* src = feat + ((size_t)(b*256 + c0 + cg*8))*S2 + ys*S + xs;
            #pragma unroll
            for (int j = 0; j < 8; j++) v[j] = src[(size_t)j*S2];
        } else {
            #pragma unroll
            for (int j = 0; j < 8; j++) v[j] = 0.f;
        }
        rau[buf][0] = packh2(v[0], v[1]);
        rau[buf][1] = packh2(v[2], v[3]);
        rau[buf][2] = packh2(v[4], v[5]);
        rau[buf][3] = packh2(v[6], v[7]);
    };
    auto issueB = [&](int ck){
        const int pos = ck >> 3;
        const int c0  = (ck & 7) << 5;
        const __half* src = g_wfh + (((size_t)pos*256 + brow) << 8) + c0 + khalf*16;
        const uint32_t dst = smb + B_BASE + (uint32_t)(ck % 3)*B_STG + brow*APITCH + khalf*32;
        cpa16(dst, src);
        cpa16(dst + 16, src + 8);
        CP_COMMIT();
    };

    loadA(0, 0);
    loadA(1, 1);
    issueB(0);
    issueB(1);

    // ldmatrix lane address components (validated mapping)
    const int arow  = (lane & 7) + ((lane >> 3) & 1) * 8;
    const int acol  = ((lane >> 4) & 1) * 16;
    const int browL = (lane & 7) + ((lane >> 4) & 1) * 8;
    const int bcolL = ((lane >> 3) & 1) * 16;

    #pragma unroll 1
    for (int ck = 0; ck < 72; ck++) {
        const uint32_t aStage = smb + (uint32_t)(ck & 1) * A_STG;
        const uint32_t bStage = smb + B_BASE + (uint32_t)(ck % 3) * B_STG;
        __syncthreads();
        if (isA) {   // STS A: 16B at row p, cin group cg
            *(uint4*)(smc + (aStage - smb) + p*APITCH + cg*16) =
                make_uint4(rau[ck & 1][0], rau[ck & 1][1], rau[ck & 1][2], rau[ck & 1][3]);
        }
        if (ck + 2 < 72) {
            loadA(ck + 2, ck & 1);
            issueB(ck + 2);
            asm volatile("cp.async.wait_group 2;" ::: "memory");
        } else if (ck + 1 < 72) {
            asm volatile("cp.async.wait_group 1;" ::: "memory");
        } else {
            asm volatile("cp.async.wait_group 0;" ::: "memory");
        }
        __syncthreads();

        #pragma unroll
        for (int ks = 0; ks < 2; ks++) {
            uint32_t af[4];
            ldsm4(aStage + (mwp*16 + arow)*APITCH + ks*32 + acol, af);
            #pragma unroll
            for (int pq = 0; pq < 4; pq++) {
                uint32_t bf[4];
                ldsm4(bStage + (nwp*64 + pq*16 + browL)*APITCH + ks*32 + bcolL, bf);
                MMAH(acc[2*pq],     af[0], af[1], af[2], af[3], bf[0], bf[1]);
                MMAH(acc[2*pq + 1], af[0], af[1], af[2], af[3], bf[2], bf[3]);
            }
        }
    }

    // epilogue: obj logits only (atomics reduce over nwp/t4/nb)
    __syncthreads();
    float* sacc = (float*)smc;            // [64][3]
    if (tid < 192) sacc[tid] = 0.f;
    __syncthreads();

    {
        const int r0 = mwp*16 + g;
        float pr[2][3] = {{0,0,0},{0,0,0}};
        #pragma unroll
        for (int nb = 0; nb < 8; nb++) {
            const int c0 = nwp*64 + nb*8 + 2*t4;
            const float b0 = bstem[c0], b1 = bstem[c0+1];
            const float s0 = fmaxf(acc[nb][0] + b0, 0.f);
            const float s1 = fmaxf(acc[nb][1] + b1, 0.f);
            const float s2 = fmaxf(acc[nb][2] + b0, 0.f);
            const float s3 = fmaxf(acc[nb][3] + b1, 0.f);
            #pragma unroll
            for (int a = 0; a < 3; a++) {
                const float w0 = g_wh[a*256 + c0], w1 = g_wh[a*256 + c0 + 1];
                pr[0][a] = fmaf(s0, w0, fmaf(s1, w1, pr[0][a]));
                pr[1][a] = fmaf(s2, w0, fmaf(s3, w1, pr[1][a]));
            }
        }
        #pragma unroll
        for (int a = 0; a < 3; a++) {
            atomicAdd(&sacc[r0*3 + a], pr[0][a]);
            atomicAdd(&sacc[(r0+8)*3 + a], pr[1][a]);
        }
    }
    __syncthreads();

    if (tid < 192) {
        int n = tid / 3, a = tid - n*3;
        g_scores[b*NTOT + loff + (tile*64 + n)*3 + a] = sacc[tid] + g_bh[a];
    }
}

// ---------------- approx top-CAND per (level,b): indices only ----------------
__global__ void topk_kernel() {
    int bl = blockIdx.x;
    int level = bl >> 2, b = bl & 3;
    int N, off;
    if (level == 0)      { N = N3; off = 0;       }
    else if (level == 1) { N = N4; off = N3;      }
    else                 { N = N5; off = N3 + N4; }
    const float* sc = g_scores + b*NTOT + off;

    __shared__ unsigned hist[4096];
    __shared__ unsigned long long cand[2048];
    __shared__ int sT, scnt;
    int tid = threadIdx.x;   // 1024

    for (int i = tid; i < 4096; i += 1024) hist[i] = 0;
    if (tid == 0) scnt = 0;
    __syncthreads();
    for (int i = tid; i < N; i += 1024)
        atomicAdd(&hist[f2o(sc[i]) >> 20], 1u);
    __syncthreads();
    if (tid == 0) {
        unsigned cum = 0; int T = 0;
        for (int bin = 4095; bin >= 0; bin--) {
            cum += hist[bin];
            if (cum >= CAND) { T = bin; break; }
        }
        sT = T;
    }
    __syncthreads();
    int T = sT;
    for (int i = tid; i < N; i += 1024) {
        unsigned u = f2o(sc[i]);
        if ((int)(u >> 20) >= T) {
            int p = atomicAdd(&scnt, 1);
            if (p < 2048)
                cand[p] = ((unsigned long long)u << 32) | (unsigned)(~i);
        }
    }
    __syncthreads();
    int cnt = min(scnt, 2048);
    for (int i = cnt + tid; i < 2048; i += 1024) cand[i] = 0ull;
    __syncthreads();

    for (int k = 2; k <= 2048; k <<= 1) {
        for (int j = k >> 1; j > 0; j >>= 1) {
            for (int i = tid; i < 2048; i += 1024) {
                int ixj = i ^ j;
                if (ixj > i) {
                    bool desc = ((i & k) == 0);
                    unsigned long long a = cand[i], c = cand[ixj];
                    bool sw = desc ? (a < c) : (a > c);
                    if (sw) { cand[i] = c; cand[ixj] = a; }
                }
            }
            __syncthreads();
        }
    }

    if (tid < CAND) {
        unsigned idx = ~(unsigned)(cand[tid] & 0xFFFFFFFFu);
        g_cidx[bl*CAND + tid] = (int)idx;
    }
}

// ---------------- exact rescue (FFMA2, round-1 K-order, 16-cin steps, 2-deep prefetch) ----------------
__global__ __launch_bounds__(256, 2)
void rescue_kernel(const float* __restrict__ f3, const float* __restrict__ f4,
                   const float* __restrict__ f5, const float* __restrict__ bstem) {
    extern __shared__ float sm[];
    float* As = sm;                   // [2][16][256]
    float* Bs = sm + 2*16*256;        // [2][16][32]
    float* st = sm;                   // epilogue: stem [256][33]
    float* wh = sm + 256*33;          //           head w [16][256]
    float* hs = sm + 256*33 + 4096;   //           head out [16][33]

    const int blk = blockIdx.x;       // 240 = 12 * 20
    const int bl  = blk / 20;
    const int seg = blk % 20;
    const int level = bl >> 2, b = bl & 3;
    int S, logS, stride;
    const float* feat;
    if (level == 0)      { S=128; logS=7; stride=8;  feat=f3; }
    else if (level == 1) { S=64;  logS=6; stride=16; feat=f4; }
    else                 { S=32;  logS=5; stride=32; feat=f5; }
    const int slotbase = bl*CAND + seg*RSEG;

    const int tid = threadIdx.x;
    const int m0  = (tid >> 2) * 4;   // cout group (0..252)
    const int n0  = (tid & 3) * 8;    // px group (0,8,16,24)
    const int px  = tid & 31;         // B loader pixel
    const int kb  = tid >> 5;         // B loader k (0..7); also handles k+8
    const int aidxL = g_cidx[slotbase + px];
    const int pixLd = aidxL / 3;
    const int ph  = pixLd >> logS;
    const int pw  = pixLd & (S - 1);
    const int SS2 = logS + logS;

    unsigned long long acc2[4][4];
    #pragma unroll
    for (int i = 0; i < 4; i++)
        #pragma unroll
        for (int j = 0; j < 4; j++) acc2[i][j] = 0ull;

    float ra[2][16], rb0[2], rb1[2];
    auto load_step = [&](int s, int buf) {
        int pos = s >> 4;
        int c0  = (s & 15) << 4;
        const float* wrow = g_wt + (pos << 16) + (c0 << 8) + tid;
        #pragma unroll
        for (int i = 0; i < 16; i++) ra[buf][i] = wrow[i << 8];
        int kh = pos / 3;
        int dh = kh - 1, dw = pos - kh*3 - 1;
        int y = ph + dh, x = pw + dw;
        rb0[buf] = 0.f; rb1[buf] = 0.f;
        if ((unsigned)y < (unsigned)S && (unsigned)x < (unsigned)S) {
            const float* fb = feat + (size_t)(((b << 8) + c0 + kb) << SS2) + (y << logS) + x;
            rb0[buf] = fb[0];
            rb1[buf] = fb[(size_t)8 << SS2];
        }
    };

    load_step(0, 0);
    load_step(1, 1);
    for (int s = 0; s < 144; s++) {
        int buf = s & 1;
        __syncthreads();
        {
            float* Aw = As + buf*16*256;
            float* Bw = Bs + buf*16*32;
            #pragma unroll
            for (int i = 0; i < 16; i++) Aw[i*256 + tid] = ra[buf][i];
            Bw[kb*32 + px]       = rb0[buf];
            Bw[(kb + 8)*32 + px] = rb1[buf];
        }
        if (s + 2 < 144) load_step(s + 2, buf);
        __syncthreads();
        const float* Ak = As + buf*16*256;
        const float* Bk = Bs + buf*16*32;
        #pragma unroll
        for (int k = 0; k < 16; k++) {
            const float4 av = *(const float4*)(Ak + k*256 + m0);
            unsigned long long b2[4];
            #pragma unroll
            for (int j = 0; j < 4; j++)
                b2[j] = *(const unsigned long long*)(Bk + k*32 + n0 + 2*j);
            const float avv[4] = {av.x, av.y, av.z, av.w};
            #pragma unroll
            for (int i = 0; i < 4; i++) {
                unsigned long long sp;
                SPLAT2(sp, avv[i]);
                FMA2(acc2[i][0], sp, b2[0]);
                FMA2(acc2[i][1], sp, b2[1]);
                FMA2(acc2[i][2], sp, b2[2]);
                FMA2(acc2[i][3], sp, b2[3]);
            }
        }
    }
    __syncthreads();

    // bias + relu -> st[cout][px], pitch 33
    #pragma unroll
    for (int i = 0; i < 4; i++) {
        float bsv = bstem[m0 + i];
        #pragma unroll
        for (int j = 0; j < 4; j++) {
            unsigned u0, u1;
            asm("mov.b64 {%0, %1}, %2;" : "=r"(u0), "=r"(u1) : "l"(acc2[i][j]));
            st[(m0 + i)*33 + (n0 + 2*j)]     = fmaxf(__uint_as_float(u0) + bsv, 0.f);
            st[(m0 + i)*33 + (n0 + 2*j + 1)] = fmaxf(__uint_as_float(u1) + bsv, 0.f);
        }
    }
    for (int i = tid; i < 16*256; i += 256) wh[i] = g_wh[i];
    __syncthreads();

    {   // head GEMM: rows og*4..+3 x 32 px
        int og = tid >> 6;
        int n  = tid & 63;
        if (n < 32) {
            float h0 = 0.f, h1 = 0.f, h2 = 0.f, h3 = 0.f;
            const float* w0 = wh + (og*4 + 0)*256;
            const float* w1 = wh + (og*4 + 1)*256;
            const float* w2 = wh + (og*4 + 2)*256;
            const float* w3 = wh + (og*4 + 3)*256;
            #pragma unroll 4
            for (int k = 0; k < 256; k++) {
                float sv = st[k*33 + n];
                h0 = fmaf(w0[k], sv, h0);
                h1 = fmaf(w1[k], sv, h1);
                h2 = fmaf(w2[k], sv, h2);
                h3 = fmaf(w3[k], sv, h3);
            }
            hs[(og*4 + 0)*33 + n] = h0 + g_bh[og*4 + 0];
            hs[(og*4 + 1)*33 + n] = h1 + g_bh[og*4 + 1];
            hs[(og*4 + 2)*33 + n] = h2 + g_bh[og*4 + 2];
            hs[(og*4 + 3)*33 + n] = h3 + g_bh[og*4 + 3];
        }
    }
    __syncthreads();

    if (tid < RSEG) {
        const int aidx = g_cidx[slotbase + tid];
        const int pixel = aidx / 3;
        const int a = aidx - pixel*3;
        const int n = tid;
        int hh = pixel >> logS, ww = pixel & (S - 1);
        float sF   = (float)stride;
        float side = 8.0f * sF;
        float area = side * side;
        float arat = (a == 0) ? 0.5f : (a == 1 ? 1.0f : 2.0f);
        float wsz  = sqrtf(area / arat);
        float hsz  = area / wsz;
        float xc = (ww + 0.5f) * sF, yc = (hh + 0.5f) * sF;
        float x1 = xc - wsz*0.5f, x2 = xc + wsz*0.5f;
        float y1 = yc - hsz*0.5f, y2 = yc + hsz*0.5f;
        float aw = x2 - x1, ah = y2 - y1;
        float acx = x1 + 0.5f*aw, acy = y1 + 0.5f*ah;

        float dx = hs[(3 + a*4 + 0)*33 + n];
        float dy = hs[(3 + a*4 + 1)*33 + n];
        float dw = fminf(hs[(3 + a*4 + 2)*33 + n], SCLAMP);
        float dh = fminf(hs[(3 + a*4 + 3)*33 + n], SCLAMP);
        float pcx = dx*aw + acx, pcy = dy*ah + acy;
        float pwd = expf(dw)*aw, phd = expf(dh)*ah;
        float bx1 = fminf(fmaxf(pcx - 0.5f*pwd, 0.f), IMGW);
        float by1 = fminf(fmaxf(pcy - 0.5f*phd, 0.f), IMGH);
        float bx2 = fminf(fmaxf(pcx + 0.5f*pwd, 0.f), IMGW);
        float by2 = fminf(fmaxf(pcy + 0.5f*phd, 0.f), IMGH);

        g_cscore[slotbase + tid] = hs[a*33 + n];
        *(float4*)(g_cbox + (size_t)(slotbase + tid)*4) = make_float4(bx1, by1, bx2, by2);
    }
}

// ---------------- final: exact top-400 among candidates + greedy NMS + emit ----------------
__global__ void final_kernel(float* __restrict__ out) {
    int bl = blockIdx.x;
    int level = bl >> 2, b = bl & 3;
    __shared__ unsigned long long key[1024];
    __shared__ int pay[1024];
    __shared__ float bx[PRE][4];
    __shared__ float ar_[PRE];
    __shared__ int keep[PRE];
    __shared__ int ord[PRE];
    __shared__ int ktot;
    int tid = threadIdx.x;   // 1024

    if (tid < CAND) {
        float s = g_cscore[bl*CAND + tid];
        int aidx = g_cidx[bl*CAND + tid];
        key[tid] = ((unsigned long long)f2o(s) << 32) | (unsigned)(~(unsigned)aidx);
        pay[tid] = tid;
    } else { key[tid] = 0ull; pay[tid] = 0; }
    __syncthreads();

    for (int k = 2; k <= 1024; k <<= 1) {
        for (int j = k >> 1; j > 0; j >>= 1) {
            int i = tid, ixj = i ^ j;
            if (ixj > i) {
                bool desc = ((i & k) == 0);
                unsigned long long a = key[i], c = key[ixj];
                if (desc ? (a < c) : (a > c)) {
                    key[i] = c; key[ixj] = a;
                    int t = pay[i]; pay[i] = pay[ixj]; pay[ixj] = t;
                }
            }
            __syncthreads();
        }
    }

    if (tid < PRE) {
        int sl = pay[tid];
        float4 v = *(const float4*)(g_cbox + (size_t)(bl*CAND + sl)*4);
        bx[tid][0] = v.x; bx[tid][1] = v.y; bx[tid][2] = v.z; bx[tid][3] = v.w;
        ar_[tid] = (v.z - v.x) * (v.w - v.y);
        keep[tid] = 1;
    }
    __syncthreads();

    for (int i = 0; i < PRE; i++) {
        if (keep[i] && tid > i && tid < PRE && keep[tid]) {
            float xx1 = fmaxf(bx[i][0], bx[tid][0]);
            float yy1 = fmaxf(bx[i][1], bx[tid][1]);
            float xx2 = fminf(bx[i][2], bx[tid][2]);
            float yy2 = fminf(bx[i][3], bx[tid][3]);
            float w = fmaxf(xx2 - xx1, 0.f);
            float h = fmaxf(yy2 - yy1, 0.f);
            float inter = w * h;
            float uni = fmaxf(ar_[i] + ar_[tid] - inter, 1e-8f);
            if (inter / uni > NMS_T) keep[tid] = 0;
        }
        __syncthreads();
    }

    if (tid == 0) {
        int cnt = 0;
        for (int i = 0; i < PRE; i++) {
            if (keep[i] && cnt < POST) { ord[i] = cnt; cnt++; }
            else ord[i] = -1;
        }
        ktot = cnt;
    }
    __syncthreads();

    float* obase = out + (size_t)(b*300 + level*100)*4;
    if (tid < PRE && ord[tid] >= 0)
        *(float4*)(obase + (size_t)ord[tid]*4) =
            make_float4(bx[tid][0], bx[tid][1], bx[tid][2], bx[tid][3]);
    if (tid < POST && tid >= ktot)
        *(float4*)(obase + (size_t)tid*4) = make_float4(0.f, 0.f, 0.f, 0.f);
}

// ---------------- launcher ----------------
extern "C" void kernel_launch(void* const* d_in, const int* in_sizes, int n_in,
                              void* d_out, int out_size) {
    const float* f3   = (const float*)d_in[0];
    const float* f4   = (const float*)d_in[1];
    const float* f5   = (const float*)d_in[2];
    const float* wst  = (const float*)d_in[3];
    const float* bst  = (const float*)d_in[4];
    const float* wobj = (const float*)d_in[5];
    const float* bobj = (const float*)d_in[6];
    const float* wbox = (const float*)d_in[7];
    const float* bbox = (const float*)d_in[8];
    float* out = (float*)d_out;
    (void)in_sizes; (void)n_in; (void)out_size;

    cudaFuncSetAttribute(aconv_kernel,  cudaFuncAttributeMaxDynamicSharedMemorySize, ACONV_SMEM);
    cudaFuncSetAttribute(rescue_kernel, cudaFuncAttributeMaxDynamicSharedMemorySize, RESCUE_SMEM);

    prep_w<<<(9*256*256 + 255)/256, 256>>>(wst);
    prep_head<<<16, 256>>>(wobj, bobj, wbox, bbox);
    aconv_kernel<<<1344, 512, ACONV_SMEM>>>(f3, f4, f5, bst);
    topk_kernel<<<12, 1024>>>();
    rescue_kernel<<<240, 256, RESCUE_SMEM>>>(f3, f4, f5, bst);
    final_kernel<<<12, 1024>>>(out);
}

// round 17
// speedup vs baseline: 1.2738x; 1.2738x over previous
#include <cuda_runtime.h>
#include <cuda_fp16.h>
#include <math.h>
#include <stdint.h>

// ---------------- problem constants ----------------
static constexpr int Bn  = 4;
static constexpr int N3  = 128*128*3;        // 49152
static constexpr int N4  = 64*64*3;          // 12288
static constexpr int N5  = 32*32*3;          // 3072
static constexpr int NTOT = N3 + N4 + N5;    // 64512
static constexpr int PRE  = 400;
static constexpr int POST = 100;
static constexpr int CAND = 640;             // approx candidate margin
static constexpr int RSEG = 32;              // rescue candidates per CTA
static constexpr float NMS_T  = 0.7f;
static constexpr float IMGW   = 1024.0f;
static constexpr float IMGH   = 1024.0f;
#define SCLAMP 3.3322045101752038f

// approx conv smem (fp16, 32-cin chunks, 128-px tiles):
// A [128 px][32 cin] pitch 80B, B [256 cout][32 cin] pitch 80B
static constexpr int APITCH = 80;
static constexpr int A_OFF  = 0;                 // 128*80 = 10240
static constexpr int B_OFF  = 10240;             // 256*80 = 20480
static constexpr int STAGE_B = 30720;
static constexpr int ACONV_SMEM = 2*STAGE_B;     // 61440
// rescue smem: stages As[2][16][256] + Bs[2][16][32]; epilogue st[256][33]+wh[4096]+hs[16*33]
static constexpr int RESCUE_SMEM = (256*33 + 4096 + 16*33) * 4;  // 52288 (> stage 36864)

// ---------------- device scratch (total ~4.7 MiB; big globals trip the mem guard) ----------------
__device__ __align__(128) float  g_wt [9*256*256];  // [pos][cin][cout] exact rescue
__device__ __align__(128) __half g_wfh[9*256*256];  // [pos][cout][cin] fp16 approx
__device__ float g_wh[16*256];        // head rows: 0..2 obj, 3..14 box, 15 zero
__device__ float g_bh[16];
__device__ float g_scores[Bn*NTOT];
__device__ int   g_cidx  [12*CAND];
__device__ float g_cscore[12*CAND];
__device__ float g_cbox  [12*CAND*4];

// packed fp32x2 FMA (exact IEEE per lane)
#define FMA2(ACC, S, B) \
    asm("fma.rn.f32x2 %0, %1, %2, %0;" : "+l"(ACC) : "l"(S), "l"(B))
#define SPLAT2(D, V) \
    asm("mov.b64 %0, {%1, %1};" : "=l"(D) : "r"(__float_as_uint(V)))

// fp16 mma m16n8k16, fp32 accumulate
#define MMAH(C, A0, A1, A2, A3, B0, B1) \
    asm volatile("mma.sync.aligned.m16n8k16.row.col.f32.f16.f16.f32 " \
        "{%0,%1,%2,%3}, {%4,%5,%6,%7}, {%8,%9}, {%0,%1,%2,%3};" \
        : "+f"((C)[0]), "+f"((C)[1]), "+f"((C)[2]), "+f"((C)[3]) \
        : "r"(A0), "r"(A1), "r"(A2), "r"(A3), "r"(B0), "r"(B1))

__device__ __forceinline__ void ldsm4(uint32_t a, uint32_t* r){
    asm volatile("ldmatrix.sync.aligned.m8n8.x4.shared.b16 {%0,%1,%2,%3}, [%4];"
                 : "=r"(r[0]), "=r"(r[1]), "=r"(r[2]), "=r"(r[3]) : "r"(a));
}
__device__ __forceinline__ uint32_t smem_u32(const void* p){
    uint32_t a;
    asm("{ .reg .u64 t; cvta.to.shared.u64 t, %1; cvt.u32.u64 %0, t; }" : "=r"(a) : "l"(p));
    return a;
}
__device__ __forceinline__ uint32_t packh2(float a, float b){
    __half2 h = __floats2half2_rn(a, b);
    return *reinterpret_cast<uint32_t*>(&h);
}
__device__ __forceinline__ unsigned f2o(float f) {
    unsigned u = __float_as_uint(f);
    return (u & 0x80000000u) ? ~u : (u | 0x80000000u);
}

// ---------------- prep ----------------
__global__ void prep_w(const float* __restrict__ w) {
    int i = blockIdx.x * 256 + threadIdx.x;
    if (i < 9*256*256) {
        int pos  = i >> 16;
        int cin  = (i >> 8) & 255;
        int cout = i & 255;
        float v = w[(cout*256 + cin)*9 + pos];
        g_wt [(pos << 16) | (cin << 8) | cout] = v;
        g_wfh[(pos << 16) | (cout << 8) | cin] = __float2half_rn(v);
    }
}

__global__ void prep_head(const float* __restrict__ wobj, const float* __restrict__ bobj,
                          const float* __restrict__ wbox, const float* __restrict__ bbox) {
    int i = blockIdx.x * 256 + threadIdx.x;
    if (i < 16*256) {
        int o = i >> 8, k = i & 255;
        float v = 0.f;
        if (o < 3)        v = wobj[o*256 + k];
        else if (o < 15)  v = wbox[(o-3)*256 + k];
        g_wh[i] = v;
    }
    if (i < 16) {
        float v = 0.f;
        if (i < 3)        v = bobj[i];
        else if (i < 15)  v = bbox[i-3];
        g_bh[i] = v;
    }
}

// ---------------- approx conv: fp16 mma + ldmatrix, 128-px tiles -> obj logits ----------------
__global__ __launch_bounds__(512)
void aconv_kernel(const float* __restrict__ f3, const float* __restrict__ f4,
                  const float* __restrict__ f5, const float* __restrict__ bstem)
{
    extern __shared__ __align__(128) char smc[];
    const uint32_t smb = smem_u32(smc);
    const int tid  = threadIdx.x;
    const int lane = tid & 31;
    const int wid  = tid >> 5;          // 0..15
    const int mwp  = wid >> 1;          // 0..7 : 16-pixel band
    const int nwp  = wid & 1;           // 0..1 : 128-cout half
    const int g    = lane >> 2;         // 0..7
    const int t4   = lane & 3;          // 0..3

    int mt = blockIdx.x;
    int b, tile, S, logS, loff;
    const float* feat;
    if (mt < 512)       { b = mt >> 7; tile = mt & 127; S=128; logS=7; loff=0;     feat = f3; }
    else if (mt < 640)  { mt -= 512; b = mt >> 5; tile = mt & 31; S=64; logS=6; loff=N3;    feat = f4; }
    else                { mt -= 640; b = mt >> 3; tile = mt & 7;  S=32; logS=5; loff=N3+N4; feat = f5; }
    const int S2 = S * S;

    const int brow  = tid & 255;        // B loader: cout row
    const int khalf = tid >> 8;         // 0/1: 16-cin half of 32-cin chunk
    const int p  = tid & 127;           // A loader: pixel
    const int cg = tid >> 7;            // 0..3: 8-cin group
    const int pixL = tile*128 + p;
    const int y0 = pixL >> logS;
    const int x0 = pixL & (S - 1);

    float acc[16][4];
    #pragma unroll
    for (int j = 0; j < 16; j++)
        #pragma unroll
        for (int k = 0; k < 4; k++) acc[j][k] = 0.f;

    uint4 rbu0, rbu1;
    uint32_t rau[4];
    auto loadregs = [&](int ck){
        const int pos = ck >> 3;
        const int c0  = (ck & 7) << 5;
        {   // B: 16 halfs (32B) of cout row brow
            const __half* src = g_wfh + (((size_t)pos*256 + brow) << 8) + c0 + khalf*16;
            rbu0 = *reinterpret_cast<const uint4*>(src);
            rbu1 = *reinterpret_cast<const uint4*>(src + 8);
        }
        {   // A: 8 fp32 cins of pixel p, halo-masked, pack to half2
            const int kh = pos / 3;
            const int dh = kh - 1, dw = pos - kh*3 - 1;
            const int ys = y0 + dh, xs = x0 + dw;
            float v[8];
            if ((unsigned)ys < (unsigned)S && (unsigned)xs < (unsigned)S) {
                const float* src = feat + ((size_t)(b*256 + c0 + cg*8))*S2 + ys*S + xs;
                #pragma unroll
                for (int j = 0; j < 8; j++) v[j] = src[(size_t)j*S2];
            } else {
                #pragma unroll
                for (int j = 0; j < 8; j++) v[j] = 0.f;
            }
            rau[0] = packh2(v[0], v[1]);
            rau[1] = packh2(v[2], v[3]);
            rau[2] = packh2(v[4], v[5]);
            rau[3] = packh2(v[6], v[7]);
        }
    };

    loadregs(0);

    // ldmatrix lane address components (validated mapping)
    const int arow  = (lane & 7) + ((lane >> 3) & 1) * 8;
    const int acol  = ((lane >> 4) & 1) * 16;
    const int browL = (lane & 7) + ((lane >> 4) & 1) * 8;
    const int bcolL = ((lane >> 3) & 1) * 16;

    #pragma unroll 1
    for (int ck = 0; ck < 72; ck++) {
        const uint32_t stg = smb + (uint32_t)(ck & 1) * STAGE_B;
        char* stc = smc + (stg - smb);
        __syncthreads();
        {   // STS B: 32B at row brow, k-half khalf
            char* bb = stc + B_OFF + brow*APITCH + khalf*32;
            *(uint4*)(bb)      = rbu0;
            *(uint4*)(bb + 16) = rbu1;
        }
        {   // STS A: 16B at row p, cin group cg
            *(uint4*)(stc + A_OFF + p*APITCH + cg*16) =
                make_uint4(rau[0], rau[1], rau[2], rau[3]);
        }
        __syncthreads();
        if (ck + 1 < 72) loadregs(ck + 1);

        #pragma unroll
        for (int ks = 0; ks < 2; ks++) {
            uint32_t af[4];
            ldsm4(stg + A_OFF + (mwp*16 + arow)*APITCH + ks*32 + acol, af);
            #pragma unroll
            for (int pq = 0; pq < 8; pq++) {
                uint32_t bf[4];
                ldsm4(stg + B_OFF + (nwp*128 + pq*16 + browL)*APITCH + ks*32 + bcolL, bf);
                MMAH(acc[2*pq],     af[0], af[1], af[2], af[3], bf[0], bf[1]);
                MMAH(acc[2*pq + 1], af[0], af[1], af[2], af[3], bf[2], bf[3]);
            }
        }
    }

    // epilogue: obj logits only (atomics reduce over nwp/t4/nb)
    __syncthreads();
    float* sacc = (float*)smc;            // [128][3]
    if (tid < 384) sacc[tid] = 0.f;
    __syncthreads();

    {
        const int r0 = mwp*16 + g;
        float pr[2][3] = {{0,0,0},{0,0,0}};
        #pragma unroll
        for (int nb = 0; nb < 16; nb++) {
            const int c0 = nwp*128 + nb*8 + 2*t4;
            const float b0 = bstem[c0], b1 = bstem[c0+1];
            const float s0 = fmaxf(acc[nb][0] + b0, 0.f);
            const float s1 = fmaxf(acc[nb][1] + b1, 0.f);
            const float s2 = fmaxf(acc[nb][2] + b0, 0.f);
            const float s3 = fmaxf(acc[nb][3] + b1, 0.f);
            #pragma unroll
            for (int a = 0; a < 3; a++) {
                const float w0 = g_wh[a*256 + c0], w1 = g_wh[a*256 + c0 + 1];
                pr[0][a] = fmaf(s0, w0, fmaf(s1, w1, pr[0][a]));
                pr[1][a] = fmaf(s2, w0, fmaf(s3, w1, pr[1][a]));
            }
        }
        #pragma unroll
        for (int a = 0; a < 3; a++) {
            atomicAdd(&sacc[r0*3 + a], pr[0][a]);
            atomicAdd(&sacc[(r0+8)*3 + a], pr[1][a]);
        }
    }
    __syncthreads();

    if (tid < 384) {
        int n = tid / 3, a = tid - n*3;
        g_scores[b*NTOT + loff + (tile*128 + n)*3 + a] = sacc[tid] + g_bh[a];
    }
}

// ---------------- approx top-CAND per (level,b): indices only ----------------
__global__ void topk_kernel() {
    int bl = blockIdx.x;
    int level = bl >> 2, b = bl & 3;
    int N, off;
    if (level == 0)      { N = N3; off = 0;       }
    else if (level == 1) { N = N4; off = N3;      }
    else                 { N = N5; off = N3 + N4; }
    const float* sc = g_scores + b*NTOT + off;

    __shared__ unsigned hist[4096];
    __shared__ unsigned long long cand[2048];
    __shared__ int sT, scnt;
    int tid = threadIdx.x;   // 1024

    for (int i = tid; i < 4096; i += 1024) hist[i] = 0;
    if (tid == 0) scnt = 0;
    __syncthreads();
    for (int i = tid; i < N; i += 1024)
        atomicAdd(&hist[f2o(sc[i]) >> 20], 1u);
    __syncthreads();
    if (tid == 0) {
        unsigned cum = 0; int T = 0;
        for (int bin = 4095; bin >= 0; bin--) {
            cum += hist[bin];
            if (cum >= CAND) { T = bin; break; }
        }
        sT = T;
    }
    __syncthreads();
    int T = sT;
    for (int i = tid; i < N; i += 1024) {
        unsigned u = f2o(sc[i]);
        if ((int)(u >> 20) >= T) {
            int p = atomicAdd(&scnt, 1);
            if (p < 2048)
                cand[p] = ((unsigned long long)u << 32) | (unsigned)(~i);
        }
    }
    __syncthreads();
    int cnt = min(scnt, 2048);
    for (int i = cnt + tid; i < 2048; i += 1024) cand[i] = 0ull;
    __syncthreads();

    for (int k = 2; k <= 2048; k <<= 1) {
        for (int j = k >> 1; j > 0; j >>= 1) {
            for (int i = tid; i < 2048; i += 1024) {
                int ixj = i ^ j;
                if (ixj > i) {
                    bool desc = ((i & k) == 0);
                    unsigned long long a = cand[i], c = cand[ixj];
                    bool sw = desc ? (a < c) : (a > c);
                    if (sw) { cand[i] = c; cand[ixj] = a; }
                }
            }
            __syncthreads();
        }
    }

    if (tid < CAND) {
        unsigned idx = ~(unsigned)(cand[tid] & 0xFFFFFFFFu);
        g_cidx[bl*CAND + tid] = (int)idx;
    }
}

// ---------------- exact rescue (FFMA2, round-1 K-order, 16-cin steps): 32 cands/CTA ----------------
__global__ __launch_bounds__(256, 2)
void rescue_kernel(const float* __restrict__ f3, const float* __restrict__ f4,
                   const float* __restrict__ f5, const float* __restrict__ bstem) {
    extern __shared__ float sm[];
    float* As = sm;                   // [2][16][256]
    float* Bs = sm + 2*16*256;        // [2][16][32]
    float* st = sm;                   // epilogue: stem [256][33]
    float* wh = sm + 256*33;          //           head w [16][256]
    float* hs = sm + 256*33 + 4096;   //           head out [16][33]

    const int blk = blockIdx.x;       // 240 = 12 * 20
    const int bl  = blk / 20;
    const int seg = blk % 20;
    const int level = bl >> 2, b = bl & 3;
    int S, logS, stride;
    const float* feat;
    if (level == 0)      { S=128; logS=7; stride=8;  feat=f3; }
    else if (level == 1) { S=64;  logS=6; stride=16; feat=f4; }
    else                 { S=32;  logS=5; stride=32; feat=f5; }
    const int slotbase = bl*CAND + seg*RSEG;

    const int tid = threadIdx.x;
    const int m0  = (tid >> 2) * 4;   // cout group (0..252)
    const int n0  = (tid & 3) * 8;    // px group (0,8,16,24)
    const int px  = tid & 31;         // B loader pixel
    const int kb  = tid >> 5;         // B loader k (0..7); also handles k+8
    const int aidxL = g_cidx[slotbase + px];
    const int pixLd = aidxL / 3;
    const int ph  = pixLd >> logS;
    const int pw  = pixLd & (S - 1);
    const int SS2 = logS + logS;

    unsigned long long acc2[4][4];
    #pragma unroll
    for (int i = 0; i < 4; i++)
        #pragma unroll
        for (int j = 0; j < 4; j++) acc2[i][j] = 0ull;

    float ra[16], rb0, rb1;
    auto load_step = [&](int s) {
        int pos = s >> 4;
        int c0  = (s & 15) << 4;
        const float* wrow = g_wt + (pos << 16) + (c0 << 8) + tid;
        #pragma unroll
        for (int i = 0; i < 16; i++) ra[i] = wrow[i << 8];
        int kh = pos / 3;
        int dh = kh - 1, dw = pos - kh*3 - 1;
        int y = ph + dh, x = pw + dw;
        rb0 = 0.f; rb1 = 0.f;
        if ((unsigned)y < (unsigned)S && (unsigned)x < (unsigned)S) {
            const float* fb = feat + (size_t)(((b << 8) + c0 + kb) << SS2) + (y << logS) + x;
            rb0 = fb[0];
            rb1 = fb[(size_t)8 << SS2];
        }
    };

    load_step(0);
    for (int s = 0; s < 144; s++) {
        int buf = s & 1;
        __syncthreads();
        {
            float* Aw = As + buf*16*256;
            float* Bw = Bs + buf*16*32;
            #pragma unroll
            for (int i = 0; i < 16; i++) Aw[i*256 + tid] = ra[i];
            Bw[kb*32 + px]       = rb0;
            Bw[(kb + 8)*32 + px] = rb1;
        }
        __syncthreads();
        if (s + 1 < 144) load_step(s + 1);
        const float* Ak = As + buf*16*256;
        const float* Bk = Bs + buf*16*32;
        #pragma unroll
        for (int k = 0; k < 16; k++) {
            const float4 av = *(const float4*)(Ak + k*256 + m0);
            unsigned long long b2[4];
            #pragma unroll
            for (int j = 0; j < 4; j++)
                b2[j] = *(const unsigned long long*)(Bk + k*32 + n0 + 2*j);
            const float avv[4] = {av.x, av.y, av.z, av.w};
            #pragma unroll
            for (int i = 0; i < 4; i++) {
                unsigned long long sp;
                SPLAT2(sp, avv[i]);
                FMA2(acc2[i][0], sp, b2[0]);
                FMA2(acc2[i][1], sp, b2[1]);
                FMA2(acc2[i][2], sp, b2[2]);
                FMA2(acc2[i][3], sp, b2[3]);
            }
        }
    }
    __syncthreads();

    // bias + relu -> st[cout][px], pitch 33
    #pragma unroll
    for (int i = 0; i < 4; i++) {
        float bsv = bstem[m0 + i];
        #pragma unroll
        for (int j = 0; j < 4; j++) {
            unsigned u0, u1;
            asm("mov.b64 {%0, %1}, %2;" : "=r"(u0), "=r"(u1) : "l"(acc2[i][j]));
            st[(m0 + i)*33 + (n0 + 2*j)]     = fmaxf(__uint_as_float(u0) + bsv, 0.f);
            st[(m0 + i)*33 + (n0 + 2*j + 1)] = fmaxf(__uint_as_float(u1) + bsv, 0.f);
        }
    }
    for (int i = tid; i < 16*256; i += 256) wh[i] = g_wh[i];
    __syncthreads();

    {   // head GEMM: rows og*4..+3 x 32 px
        int og = tid >> 6;
        int n  = tid & 63;
        if (n < 32) {
            float h0 = 0.f, h1 = 0.f, h2 = 0.f, h3 = 0.f;
            const float* w0 = wh + (og*4 + 0)*256;
            const float* w1 = wh + (og*4 + 1)*256;
            const float* w2 = wh + (og*4 + 2)*256;
            const float* w3 = wh + (og*4 + 3)*256;
            #pragma unroll 4
            for (int k = 0; k < 256; k++) {
                float sv = st[k*33 + n];
                h0 = fmaf(w0[k], sv, h0);
                h1 = fmaf(w1[k], sv, h1);
                h2 = fmaf(w2[k], sv, h2);
                h3 = fmaf(w3[k], sv, h3);
            }
            hs[(og*4 + 0)*33 + n] = h0 + g_bh[og*4 + 0];
            hs[(og*4 + 1)*33 + n] = h1 + g_bh[og*4 + 1];
            hs[(og*4 + 2)*33 + n] = h2 + g_bh[og*4 + 2];
            hs[(og*4 + 3)*33 + n] = h3 + g_bh[og*4 + 3];
        }
    }
    __syncthreads();

    if (tid < RSEG) {
        const int aidx = g_cidx[slotbase + tid];
        const int pixel = aidx / 3;
        const int a = aidx - pixel*3;
        const int n = tid;
        int hh = pixel >> logS, ww = pixel & (S - 1);
        float sF   = (float)stride;
        float side = 8.0f * sF;
        float area = side * side;
        float arat = (a == 0) ? 0.5f : (a == 1 ? 1.0f : 2.0f);
        float wsz  = sqrtf(area / arat);
        float hsz  = area / wsz;
        float xc = (ww + 0.5f) * sF, yc = (hh + 0.5f) * sF;
        float x1 = xc - wsz*0.5f, x2 = xc + wsz*0.5f;
        float y1 = yc - hsz*0.5f, y2 = yc + hsz*0.5f;
        float aw = x2 - x1, ah = y2 - y1;
        float acx = x1 + 0.5f*aw, acy = y1 + 0.5f*ah;

        float dx = hs[(3 + a*4 + 0)*33 + n];
        float dy = hs[(3 + a*4 + 1)*33 + n];
        float dw = fminf(hs[(3 + a*4 + 2)*33 + n], SCLAMP);
        float dh = fminf(hs[(3 + a*4 + 3)*33 + n], SCLAMP);
        float pcx = dx*aw + acx, pcy = dy*ah + acy;
        float pwd = expf(dw)*aw, phd = expf(dh)*ah;
        float bx1 = fminf(fmaxf(pcx - 0.5f*pwd, 0.f), IMGW);
        float by1 = fminf(fmaxf(pcy - 0.5f*phd, 0.f), IMGH);
        float bx2 = fminf(fmaxf(pcx + 0.5f*pwd, 0.f), IMGW);
        float by2 = fminf(fmaxf(pcy + 0.5f*phd, 0.f), IMGH);

        g_cscore[slotbase + tid] = hs[a*33 + n];
        *(float4*)(g_cbox + (size_t)(slotbase + tid)*4) = make_float4(bx1, by1, bx2, by2);
    }
}

// ---------------- final: exact top-400 among candidates + greedy NMS + emit ----------------
__global__ void final_kernel(float* __restrict__ out) {
    int bl = blockIdx.x;
    int level = bl >> 2, b = bl & 3;
    __shared__ unsigned long long key[1024];
    __shared__ int pay[1024];
    __shared__ float bx[PRE][4];
    __shared__ float ar_[PRE];
    __shared__ int keep[PRE];
    __shared__ int ord[PRE];
    __shared__ int ktot;
    int tid = threadIdx.x;   // 1024

    if (tid < CAND) {
        float s = g_cscore[bl*CAND + tid];
        int aidx = g_cidx[bl*CAND + tid];
        key[tid] = ((unsigned long long)f2o(s) << 32) | (unsigned)(~(unsigned)aidx);
        pay[tid] = tid;
    } else { key[tid] = 0ull; pay[tid] = 0; }
    __syncthreads();

    for (int k = 2; k <= 1024; k <<= 1) {
        for (int j = k >> 1; j > 0; j >>= 1) {
            int i = tid, ixj = i ^ j;
            if (ixj > i) {
                bool desc = ((i & k) == 0);
                unsigned long long a = key[i], c = key[ixj];
                if (desc ? (a < c) : (a > c)) {
                    key[i] = c; key[ixj] = a;
                    int t = pay[i]; pay[i] = pay[ixj]; pay[ixj] = t;
                }
            }
            __syncthreads();
        }
    }

    if (tid < PRE) {
        int sl = pay[tid];
        float4 v = *(const float4*)(g_cbox + (size_t)(bl*CAND + sl)*4);
        bx[tid][0] = v.x; bx[tid][1] = v.y; bx[tid][2] = v.z; bx[tid][3] = v.w;
        ar_[tid] = (v.z - v.x) * (v.w - v.y);
        keep[tid] = 1;
    }
    __syncthreads();

    for (int i = 0; i < PRE; i++) {
        if (keep[i] && tid > i && tid < PRE && keep[tid]) {
            float xx1 = fmaxf(bx[i][0], bx[tid][0]);
            float yy1 = fmaxf(bx[i][1], bx[tid][1]);
            float xx2 = fminf(bx[i][2], bx[tid][2]);
            float yy2 = fminf(bx[i][3], bx[tid][3]);
            float w = fmaxf(xx2 - xx1, 0.f);
            float h = fmaxf(yy2 - yy1, 0.f);
            float inter = w * h;
            float uni = fmaxf(ar_[i] + ar_[tid] - inter, 1e-8f);
            if (inter / uni > NMS_T) keep[tid] = 0;
        }
        __syncthreads();
    }

    if (tid == 0) {
        int cnt = 0;
        for (int i = 0; i < PRE; i++) {
            if (keep[i] && cnt < POST) { ord[i] = cnt; cnt++; }
            else ord[i] = -1;
        }
        ktot = cnt;
    }
    __syncthreads();

    float* obase = out + (size_t)(b*300 + level*100)*4;
    if (tid < PRE && ord[tid] >= 0)
        *(float4*)(obase + (size_t)ord[tid]*4) =
            make_float4(bx[tid][0], bx[tid][1], bx[tid][2], bx[tid][3]);
    if (tid < POST && tid >= ktot)
        *(float4*)(obase + (size_t)tid*4) = make_float4(0.f, 0.f, 0.f, 0.f);
}

// ---------------- launcher ----------------
extern "C" void kernel_launch(void* const* d_in, const int* in_sizes, int n_in,
                              void* d_out, int out_size) {
    const float* f3   = (const float*)d_in[0];
    const float* f4   = (const float*)d_in[1];
    const float* f5   = (const float*)d_in[2];
    const float* wst  = (const float*)d_in[3];
    const float* bst  = (const float*)d_in[4];
    const float* wobj = (const float*)d_in[5];
    const float* bobj = (const float*)d_in[6];
    const float* wbox = (const float*)d_in[7];
    const float* bbox = (const float*)d_in[8];
    float* out = (float*)d_out;
    (void)in_sizes; (void)n_in; (void)out_size;

    cudaFuncSetAttribute(aconv_kernel,  cudaFuncAttributeMaxDynamicSharedMemorySize, ACONV_SMEM);
    cudaFuncSetAttribute(rescue_kernel, cudaFuncAttributeMaxDynamicSharedMemorySize, RESCUE_SMEM);

    prep_w<<<(9*256*256 + 255)/256, 256>>>(wst);
    prep_head<<<16, 256>>>(wobj, bobj, wbox, bbox);
    aconv_kernel<<<672, 512, ACONV_SMEM>>>(f3, f4, f5, bst);
    topk_kernel<<<12, 1024>>>();
    rescue_kernel<<<240, 256, RESCUE_SMEM>>>(f3, f4, f5, bst);
    final_kernel<<<12, 1024>>>(out);
}